// round 5
// baseline (speedup 1.0000x reference)
#include <cuda_runtime.h>
#include <cuda_bf16.h>
#include <mma.h>
#include <cstdint>

using namespace nvcuda;

// Problem constants
#define BB 4
#define NN 4096
#define DIMM 1024
#define HH 16
#define HDD 64
#define MM (BB * NN)           // 16384 rows

// ---------------- scratch (device globals; no allocation allowed) ----------
__device__ float g_Q[(size_t)MM * DIMM];
__device__ float g_K[(size_t)MM * DIMM];
__device__ float g_V[(size_t)MM * DIMM];
__device__ float g_A[(size_t)MM * DIMM];
__device__ float g_Rq[(size_t)MM * DIMM];
__device__ float g_Rk[(size_t)MM * DIMM];
__device__ float g_Rv[(size_t)MM * DIMM];
__device__ float g_Wr[4 * DIMM * DIMM];
__device__ float g_kv[BB * HH * HDD * HDD];
__device__ float g_ksum[BB * HH * HDD];

__device__ __forceinline__ float to_tf32(float x) {
    float r;
    asm("cvt.rna.tf32.f32 %0, %1;" : "=f"(r) : "f"(x));
    return r;
}

__device__ __forceinline__ void cp_async16_s(unsigned int smem_addr, const void* gmem_ptr) {
    asm volatile("cp.async.cg.shared.global [%0], [%1], 16;\n" :: "r"(smem_addr), "l"(gmem_ptr));
}

// ---------------- tf32 rounding pass ----------------
__global__ void round_tf32_kernel(const float* __restrict__ src,
                                  float* __restrict__ dst, int n4) {
    int i = blockIdx.x * blockDim.x + threadIdx.x;
    if (i < n4) {
        float4 v = ((const float4*)src)[i];
        v.x = to_tf32(v.x); v.y = to_tf32(v.y);
        v.z = to_tf32(v.z); v.w = to_tf32(v.w);
        ((float4*)dst)[i] = v;
    }
}

// ================= WMMA tf32 GEMM, 256x128 block, 64x64 warp, 4-stage =====
// C[m,j] = act( A[m,:] . W[j,:] + bias[j] ); A, W pre-rounded to tf32.
#define BM 256
#define BN 128
#define KS 16
#define NSTAGE 4
#define NCHUNK (DIMM / KS)            // 64
#define PAD 20                        // floats per K-slice row (16 + 4)
#define A_STG_FLOATS (BM * PAD)       // 5120
#define B_STG_FLOATS (BN * PAD)       // 2560
#define STG_FLOATS (A_STG_FLOATS + B_STG_FLOATS)   // 7680
#define DSMEM_BYTES (NSTAGE * STG_FLOATS * 4)      // 122880

extern __shared__ __align__(16) float dsm[];

__global__ void __launch_bounds__(256, 1)
gemm_tc(const float* __restrict__ A, const float* __restrict__ W,
        const float* __restrict__ bias, const int* __restrict__ mask,
        float* __restrict__ C, int do_relu) {
    const int t = threadIdx.x;
    const int w = t >> 5;
    const int wm = w >> 1;            // 0..3 -> 64-row band
    const int wn = w & 1;             // 0..1 -> 64-col band
    const int n0 = blockIdx.x * BN;
    const int m0 = blockIdx.y * BM;

    const unsigned int sb = (unsigned int)__cvta_generic_to_shared(dsm);

    wmma::fragment<wmma::accumulator, 16, 16, 8, float> acc[4][4];
#pragma unroll
    for (int i = 0; i < 4; i++)
#pragma unroll
        for (int j = 0; j < 4; j++)
            wmma::fill_fragment(acc[i][j], 0.0f);

    const float* Abase = A + (size_t)m0 * DIMM;
    const float* Bbase = W + (size_t)n0 * DIMM;

    // A tile: 256x16 = 1024 float4; B tile: 128x16 = 512 float4.
    auto load_chunk = [&](int c, int s) {
        const int k0 = c * KS;
        const unsigned int abuf = sb + s * (STG_FLOATS * 4);
        const unsigned int bbuf = abuf + A_STG_FLOATS * 4;
#pragma unroll
        for (int j = 0; j < 4; j++) {
            int u = t + j * 256;
            int row = u >> 2;
            int c4 = (u & 3) * 4;
            cp_async16_s(abuf + (row * PAD + c4) * 4,
                         Abase + (size_t)row * DIMM + k0 + c4);
        }
#pragma unroll
        for (int j = 0; j < 2; j++) {
            int u = t + j * 256;
            int row = u >> 2;
            int c4 = (u & 3) * 4;
            cp_async16_s(bbuf + (row * PAD + c4) * 4,
                         Bbase + (size_t)row * DIMM + k0 + c4);
        }
    };

    // prologue: stages 0..2
#pragma unroll
    for (int c = 0; c < NSTAGE - 1; c++) {
        load_chunk(c, c);
        asm volatile("cp.async.commit_group;");
    }

    for (int i = 0; i < NCHUNK; i++) {
        const int s = i & (NSTAGE - 1);
        asm volatile("cp.async.wait_group %0;" :: "n"(NSTAGE - 2));
        __syncthreads();

        // issue next load before compute
        if (i + NSTAGE - 1 < NCHUNK) load_chunk(i + NSTAGE - 1, (i + NSTAGE - 1) & (NSTAGE - 1));
        asm volatile("cp.async.commit_group;");

        const float* As = dsm + s * STG_FLOATS;
        const float* Bs = As + A_STG_FLOATS;
#pragma unroll
        for (int kk = 0; kk < KS; kk += 8) {
            wmma::fragment<wmma::matrix_a, 16, 16, 8, wmma::precision::tf32, wmma::row_major> af[4];
            wmma::fragment<wmma::matrix_b, 16, 16, 8, wmma::precision::tf32, wmma::col_major> bf[4];
#pragma unroll
            for (int x = 0; x < 4; x++)
                wmma::load_matrix_sync(af[x], As + (wm * 64 + x * 16) * PAD + kk, PAD);
#pragma unroll
            for (int y = 0; y < 4; y++)
                wmma::load_matrix_sync(bf[y], Bs + (wn * 64 + y * 16) * PAD + kk, PAD);
#pragma unroll
            for (int x = 0; x < 4; x++)
#pragma unroll
                for (int y = 0; y < 4; y++)
                    wmma::mma_sync(acc[x][y], af[x], bf[y], acc[x][y]);
        }
        __syncthreads();
    }

    // ---- epilogue: 4 quarters of 64 rows x 128 cols via smem (ldm 132) ----
    float* Ct = dsm;   // 64*132 = 8448 floats, fits easily
#pragma unroll
    for (int q = 0; q < 4; q++) {
        if (wm == q) {
#pragma unroll
            for (int x = 0; x < 4; x++)
#pragma unroll
                for (int y = 0; y < 4; y++)
                    wmma::store_matrix_sync(Ct + (x * 16) * 132 + wn * 64 + y * 16,
                                            acc[x][y], 132, wmma::mem_row_major);
        }
        __syncthreads();
        // 64x128 = 2048 float4, 8 per thread
#pragma unroll
        for (int i = 0; i < 8; i++) {
            int u = t + i * 256;
            int r = u >> 5;
            int c = (u & 31) * 4;
            int row = m0 + q * 64 + r;
            float4 v = *(float4*)(Ct + r * 132 + c);
            v.x += bias[n0 + c + 0];
            v.y += bias[n0 + c + 1];
            v.z += bias[n0 + c + 2];
            v.w += bias[n0 + c + 3];
            if (do_relu) {
                v.x = fmaxf(v.x, 0.0f); v.y = fmaxf(v.y, 0.0f);
                v.z = fmaxf(v.z, 0.0f); v.w = fmaxf(v.w, 0.0f);
            }
            if (mask != nullptr && mask[row] != 0) {
                v.x = 0.0f; v.y = 0.0f; v.z = 0.0f; v.w = 0.0f;
            }
            *(float4*)(C + (size_t)row * DIMM + n0 + c) = v;
        }
        __syncthreads();
    }
}

// ---------------- zero kv / ksum ----------------
__global__ void zero_kernel(float* kv, float* ksum) {
    int idx = blockIdx.x * blockDim.x + threadIdx.x;
    if (idx < BB * HH * HDD * HDD) kv[idx] = 0.0f;
    if (idx < BB * HH * HDD) ksum[idx] = 0.0f;
}

// ---------------- kv[b,h,d,e] = sum_n K[b,n,h,d] * V[b,n,h,e]; ksum too ----
__global__ void __launch_bounds__(256)
kv_kernel(const float* __restrict__ K, const float* __restrict__ V,
          float* __restrict__ kv, float* __restrict__ ksum) {
    const int bh = blockIdx.y;
    const int b = bh >> 4, h = bh & 15;
    const int t = threadIdx.x;
    __shared__ float ks[4][64];
    __shared__ float vs[4][64];

    const int td = (t >> 4) << 2;
    const int te = (t & 15) << 2;
    float acc[4][4] = {};
    float ksacc = 0.0f;

    const int nbase0 = blockIdx.x * 512;
    for (int nb = 0; nb < 512; nb += 4) {
        const int n0 = nbase0 + nb;
#pragma unroll
        for (int j = 0; j < 2; j++) {
            int u = t + j * 256;
            int nn = (u >> 6) & 3;
            int d = u & 63;
            if (u < 256) {
                ks[nn][d] = K[((size_t)(b * NN + n0 + nn)) * DIMM + h * HDD + d];
            } else {
                vs[nn][d] = V[((size_t)(b * NN + n0 + nn)) * DIMM + h * HDD + d];
            }
        }
        __syncthreads();
#pragma unroll
        for (int nn = 0; nn < 4; nn++) {
            float kd0 = ks[nn][td + 0], kd1 = ks[nn][td + 1];
            float kd2 = ks[nn][td + 2], kd3 = ks[nn][td + 3];
            float ve0 = vs[nn][te + 0], ve1 = vs[nn][te + 1];
            float ve2 = vs[nn][te + 2], ve3 = vs[nn][te + 3];
            acc[0][0] += kd0 * ve0; acc[0][1] += kd0 * ve1; acc[0][2] += kd0 * ve2; acc[0][3] += kd0 * ve3;
            acc[1][0] += kd1 * ve0; acc[1][1] += kd1 * ve1; acc[1][2] += kd1 * ve2; acc[1][3] += kd1 * ve3;
            acc[2][0] += kd2 * ve0; acc[2][1] += kd2 * ve1; acc[2][2] += kd2 * ve2; acc[2][3] += kd2 * ve3;
            acc[3][0] += kd3 * ve0; acc[3][1] += kd3 * ve1; acc[3][2] += kd3 * ve2; acc[3][3] += kd3 * ve3;
        }
        if (t < 64) ksacc += ks[0][t] + ks[1][t] + ks[2][t] + ks[3][t];
        __syncthreads();
    }

#pragma unroll
    for (int i = 0; i < 4; i++)
#pragma unroll
        for (int j = 0; j < 4; j++)
            atomicAdd(&kv[((size_t)bh * HDD + (td + i)) * HDD + te + j], acc[i][j]);
    if (t < 64) atomicAdd(&ksum[bh * HDD + t], ksacc);
}

// ---------------- out = (q.kv) / (q.ksum + eps), tf32-rounded output -------
__global__ void __launch_bounds__(256)
attn_kernel(const float* __restrict__ Q, const float* __restrict__ kv,
            const float* __restrict__ ksum, float* __restrict__ out) {
    const int bh = blockIdx.y;
    const int b = bh >> 4, h = bh & 15;
    const int t = threadIdx.x;
    const int w = t >> 5, l = t & 31;

    __shared__ float kvs[64 * 64];
    __shared__ float kss[64];
    __shared__ float qs[8][64];

    for (int i = t; i < 4096; i += 256) kvs[i] = kv[(size_t)bh * 4096 + i];
    if (t < 64) kss[t] = ksum[bh * 64 + t];
    __syncthreads();

    const int nbase = blockIdx.x * 128;
    for (int it = 0; it < 16; it++) {
        const int n = nbase + it * 8 + w;
        const float* qrow = Q + ((size_t)(b * NN + n)) * DIMM + h * HDD;
        float q0 = qrow[l];
        float q1 = qrow[l + 32];
        qs[w][l] = q0;
        qs[w][l + 32] = q1;
        __syncwarp();

        float p = q0 * kss[l] + q1 * kss[l + 32];
#pragma unroll
        for (int off = 16; off; off >>= 1) p += __shfl_xor_sync(0xffffffffu, p, off);
        const float denom = 1.0f / (p + 1e-6f);

        float a0 = 0.0f, a1 = 0.0f;
#pragma unroll 8
        for (int d = 0; d < 64; d++) {
            float qd = qs[w][d];
            a0 += qd * kvs[d * 64 + l];
            a1 += qd * kvs[d * 64 + l + 32];
        }
        float* orow = out + ((size_t)(b * NN + n)) * DIMM + h * HDD;
        orow[l] = to_tf32(a0 * denom);
        orow[l + 32] = to_tf32(a1 * denom);
        __syncwarp();
    }
}

// ---------------- launch ----------------
extern "C" void kernel_launch(void* const* d_in, const int* in_sizes, int n_in,
                              void* d_out, int out_size) {
    const float* query = (const float*)d_in[0];
    const float* key   = (const float*)d_in[1];
    const float* value = (const float*)d_in[2];
    const float* Wq = (const float*)d_in[3];
    const float* bq = (const float*)d_in[4];
    const float* Wk = (const float*)d_in[5];
    const float* bk = (const float*)d_in[6];
    const float* Wv = (const float*)d_in[7];
    const float* bv = (const float*)d_in[8];
    const float* Wo = (const float*)d_in[9];
    const float* bo = (const float*)d_in[10];
    const int* mask = (const int*)d_in[11];

    float *Qp, *Kp, *Vp, *Ap, *Rq, *Rk, *Rv, *Wr, *KVp, *KSp;
    cudaGetSymbolAddress((void**)&Qp, g_Q);
    cudaGetSymbolAddress((void**)&Kp, g_K);
    cudaGetSymbolAddress((void**)&Vp, g_V);
    cudaGetSymbolAddress((void**)&Ap, g_A);
    cudaGetSymbolAddress((void**)&Rq, g_Rq);
    cudaGetSymbolAddress((void**)&Rk, g_Rk);
    cudaGetSymbolAddress((void**)&Rv, g_Rv);
    cudaGetSymbolAddress((void**)&Wr, g_Wr);
    cudaGetSymbolAddress((void**)&KVp, g_kv);
    cudaGetSymbolAddress((void**)&KSp, g_ksum);

    cudaFuncSetAttribute(gemm_tc, cudaFuncAttributeMaxDynamicSharedMemorySize, DSMEM_BYTES);

    const int n4_act = (MM * DIMM) / 4;
    const int n4_w   = (DIMM * DIMM) / 4;

    round_tf32_kernel<<<(n4_act + 255) / 256, 256>>>(query, Rq, n4_act);
    round_tf32_kernel<<<(n4_act + 255) / 256, 256>>>(key,   Rk, n4_act);
    round_tf32_kernel<<<(n4_act + 255) / 256, 256>>>(value, Rv, n4_act);
    round_tf32_kernel<<<(n4_w + 255) / 256, 256>>>(Wq, Wr + 0 * (size_t)DIMM * DIMM, n4_w);
    round_tf32_kernel<<<(n4_w + 255) / 256, 256>>>(Wk, Wr + 1 * (size_t)DIMM * DIMM, n4_w);
    round_tf32_kernel<<<(n4_w + 255) / 256, 256>>>(Wv, Wr + 2 * (size_t)DIMM * DIMM, n4_w);
    round_tf32_kernel<<<(n4_w + 255) / 256, 256>>>(Wo, Wr + 3 * (size_t)DIMM * DIMM, n4_w);

    dim3 ggrid(DIMM / BN, MM / BM);   // (8, 64) = 512 blocks

    gemm_tc<<<ggrid, 256, DSMEM_BYTES>>>(Rq, Wr + 0 * (size_t)DIMM * DIMM, bq, nullptr, Qp, 1);
    gemm_tc<<<ggrid, 256, DSMEM_BYTES>>>(Rk, Wr + 1 * (size_t)DIMM * DIMM, bk, mask,    Kp, 1);
    gemm_tc<<<ggrid, 256, DSMEM_BYTES>>>(Rv, Wr + 2 * (size_t)DIMM * DIMM, bv, nullptr, Vp, 0);

    zero_kernel<<<1024, 256>>>(KVp, KSp);
    kv_kernel<<<dim3(8, 64), 256>>>(Kp, Vp, KVp, KSp);
    attn_kernel<<<dim3(32, 64), 256>>>(Qp, KVp, KSp, Ap);

    gemm_tc<<<ggrid, 256, DSMEM_BYTES>>>(Ap, Wr + 3 * (size_t)DIMM * DIMM, bo, nullptr, (float*)d_out, 0);
}

// round 6
// speedup vs baseline: 1.0478x; 1.0478x over previous
#include <cuda_runtime.h>
#include <cuda_bf16.h>
#include <mma.h>
#include <cstdint>

using namespace nvcuda;

// Problem constants
#define BB 4
#define NN 4096
#define DIMM 1024
#define HH 16
#define HDD 64
#define MM (BB * NN)           // 16384 rows

// ---------------- scratch (device globals; no allocation allowed) ----------
__device__ float g_Q[(size_t)MM * DIMM];
__device__ float g_K[(size_t)MM * DIMM];
__device__ float g_V[(size_t)MM * DIMM];
__device__ float g_A[(size_t)MM * DIMM];
__device__ float g_Wr[4 * DIMM * DIMM];     // tf32-rounded Wq,Wk,Wv,Wo
__device__ float g_kv[BB * HH * HDD * HDD];
__device__ float g_ksum[BB * HH * HDD];

__device__ __forceinline__ float to_tf32(float x) {
    float r;
    asm("cvt.rna.tf32.f32 %0, %1;" : "=f"(r) : "f"(x));
    return r;
}

__device__ __forceinline__ void cp_async16_s(unsigned int smem_addr, const void* gmem_ptr) {
    asm volatile("cp.async.cg.shared.global [%0], [%1], 16;\n" :: "r"(smem_addr), "l"(gmem_ptr));
}

// ---------------- tf32 rounding pass (weights only) ----------------
__global__ void round_tf32_kernel(const float* __restrict__ src,
                                  float* __restrict__ dst, int n4) {
    int i = blockIdx.x * blockDim.x + threadIdx.x;
    if (i < n4) {
        float4 v = ((const float4*)src)[i];
        v.x = to_tf32(v.x); v.y = to_tf32(v.y);
        v.z = to_tf32(v.z); v.w = to_tf32(v.w);
        ((float4*)dst)[i] = v;
    }
}

// ================= WMMA tf32 GEMM, 128x128 block, K-chunk 32, 2-stage =====
// C[m,j] = act( A[m,:] . W[j,:] + bias[j] )
// W must be pre-rounded to tf32; A is rounded IN SMEM after cp.async.
#define BM 128
#define BN 128
#define KC 32
#define NCHUNK (DIMM / KC)            // 32
#define PAD 36                        // 32 + 4 floats per row slice
#define TILE_FLOATS (128 * PAD)       // 4608
#define STG_FLOATS (2 * TILE_FLOATS)  // A + B = 9216
#define DSMEM_BYTES (2 * STG_FLOATS * 4)   // 73728 (2 stages)

extern __shared__ __align__(16) float dsm[];

__global__ void __launch_bounds__(256, 2)
gemm_tc(const float* __restrict__ A, const float* __restrict__ W,
        const float* __restrict__ bias, const int* __restrict__ mask,
        float* __restrict__ C, int do_relu) {
    const int t = threadIdx.x;
    const int w = t >> 5;
    const int wm = w >> 1;            // 0..3 -> 32-row band
    const int wn = w & 1;             // 0..1 -> 64-col band
    const int n0 = blockIdx.x * BN;
    const int m0 = blockIdx.y * BM;

    const unsigned int sb = (unsigned int)__cvta_generic_to_shared(dsm);

    wmma::fragment<wmma::accumulator, 16, 16, 8, float> acc[2][4];
#pragma unroll
    for (int i = 0; i < 2; i++)
#pragma unroll
        for (int j = 0; j < 4; j++)
            wmma::fill_fragment(acc[i][j], 0.0f);

    const float* Abase = A + (size_t)m0 * DIMM;
    const float* Bbase = W + (size_t)n0 * DIMM;

    // per stage: A 128x32 floats (1024 float4) + B same; 8 float4 per thread
    auto load_chunk = [&](int c, int s) {
        const int k0 = c * KC;
        const unsigned int abuf = sb + s * (STG_FLOATS * 4);
        const unsigned int bbuf = abuf + TILE_FLOATS * 4;
#pragma unroll
        for (int j = 0; j < 4; j++) {
            int u = t + j * 256;
            int row = u >> 3;
            int c4 = (u & 7) * 4;
            cp_async16_s(abuf + (row * PAD + c4) * 4, Abase + (size_t)row * DIMM + k0 + c4);
            cp_async16_s(bbuf + (row * PAD + c4) * 4, Bbase + (size_t)row * DIMM + k0 + c4);
        }
    };

    // prologue: stage 0
    load_chunk(0, 0);
    asm volatile("cp.async.commit_group;");

    for (int i = 0; i < NCHUNK; i++) {
        const int s = i & 1;
        // issue next chunk first (into other buffer), then wait for current
        if (i + 1 < NCHUNK) {
            load_chunk(i + 1, s ^ 1);
            asm volatile("cp.async.commit_group;");
            asm volatile("cp.async.wait_group 1;");
        } else {
            asm volatile("cp.async.wait_group 0;");
        }
        __syncthreads();

        float* As = dsm + s * STG_FLOATS;
        const float* Bs = As + TILE_FLOATS;

        // round A tile to tf32 (RN) in place: 1024 float4, 4 per thread
#pragma unroll
        for (int j = 0; j < 4; j++) {
            int u = t + j * 256;
            int row = u >> 3;
            int c4 = (u & 7) * 4;
            float4 v = *(float4*)(As + row * PAD + c4);
            v.x = to_tf32(v.x); v.y = to_tf32(v.y);
            v.z = to_tf32(v.z); v.w = to_tf32(v.w);
            *(float4*)(As + row * PAD + c4) = v;
        }
        __syncthreads();

#pragma unroll
        for (int kk = 0; kk < KC; kk += 8) {
            wmma::fragment<wmma::matrix_a, 16, 16, 8, wmma::precision::tf32, wmma::row_major> af[2];
            wmma::fragment<wmma::matrix_b, 16, 16, 8, wmma::precision::tf32, wmma::col_major> bf[4];
#pragma unroll
            for (int x = 0; x < 2; x++)
                wmma::load_matrix_sync(af[x], As + (wm * 32 + x * 16) * PAD + kk, PAD);
#pragma unroll
            for (int y = 0; y < 4; y++)
                wmma::load_matrix_sync(bf[y], Bs + (wn * 64 + y * 16) * PAD + kk, PAD);
#pragma unroll
            for (int x = 0; x < 2; x++)
#pragma unroll
                for (int y = 0; y < 4; y++)
                    wmma::mma_sync(acc[x][y], af[x], bf[y], acc[x][y]);
        }
        __syncthreads();
    }

    // ---- epilogue: two 64-row halves via smem (ldm 132) ----
    float* Ct = dsm;   // 64*132 = 8448 <= 9216 floats
#pragma unroll
    for (int half = 0; half < 2; half++) {
        if ((wm >> 1) == half) {
            const int wml = wm & 1;
#pragma unroll
            for (int x = 0; x < 2; x++)
#pragma unroll
                for (int y = 0; y < 4; y++)
                    wmma::store_matrix_sync(Ct + (wml * 32 + x * 16) * 132 + wn * 64 + y * 16,
                                            acc[x][y], 132, wmma::mem_row_major);
        }
        __syncthreads();
#pragma unroll
        for (int i = 0; i < 8; i++) {
            int u = t + i * 256;
            int r = u >> 5;
            int c = (u & 31) * 4;
            int row = m0 + half * 64 + r;
            float4 v = *(float4*)(Ct + r * 132 + c);
            v.x += bias[n0 + c + 0];
            v.y += bias[n0 + c + 1];
            v.z += bias[n0 + c + 2];
            v.w += bias[n0 + c + 3];
            if (do_relu) {
                v.x = fmaxf(v.x, 0.0f); v.y = fmaxf(v.y, 0.0f);
                v.z = fmaxf(v.z, 0.0f); v.w = fmaxf(v.w, 0.0f);
            }
            if (mask != nullptr && mask[row] != 0) {
                v.x = 0.0f; v.y = 0.0f; v.z = 0.0f; v.w = 0.0f;
            }
            *(float4*)(C + (size_t)row * DIMM + n0 + c) = v;
        }
        __syncthreads();
    }
}

// ---------------- zero kv / ksum ----------------
__global__ void zero_kernel(float* kv, float* ksum) {
    int idx = blockIdx.x * blockDim.x + threadIdx.x;
    if (idx < BB * HH * HDD * HDD) kv[idx] = 0.0f;
    if (idx < BB * HH * HDD) ksum[idx] = 0.0f;
}

// ---------------- kv[b,h,d,e] = sum_n K[b,n,h,d] * V[b,n,h,e]; ksum too ----
__global__ void __launch_bounds__(256)
kv_kernel(const float* __restrict__ K, const float* __restrict__ V,
          float* __restrict__ kv, float* __restrict__ ksum) {
    const int bh = blockIdx.y;
    const int b = bh >> 4, h = bh & 15;
    const int t = threadIdx.x;
    __shared__ float ks[4][64];
    __shared__ float vs[4][64];

    const int td = (t >> 4) << 2;
    const int te = (t & 15) << 2;
    float acc[4][4] = {};
    float ksacc = 0.0f;

    const int nbase0 = blockIdx.x * 512;
    for (int nb = 0; nb < 512; nb += 4) {
        const int n0 = nbase0 + nb;
#pragma unroll
        for (int j = 0; j < 2; j++) {
            int u = t + j * 256;
            int nn = (u >> 6) & 3;
            int d = u & 63;
            if (u < 256) {
                ks[nn][d] = K[((size_t)(b * NN + n0 + nn)) * DIMM + h * HDD + d];
            } else {
                vs[nn][d] = V[((size_t)(b * NN + n0 + nn)) * DIMM + h * HDD + d];
            }
        }
        __syncthreads();
#pragma unroll
        for (int nn = 0; nn < 4; nn++) {
            float kd0 = ks[nn][td + 0], kd1 = ks[nn][td + 1];
            float kd2 = ks[nn][td + 2], kd3 = ks[nn][td + 3];
            float ve0 = vs[nn][te + 0], ve1 = vs[nn][te + 1];
            float ve2 = vs[nn][te + 2], ve3 = vs[nn][te + 3];
            acc[0][0] += kd0 * ve0; acc[0][1] += kd0 * ve1; acc[0][2] += kd0 * ve2; acc[0][3] += kd0 * ve3;
            acc[1][0] += kd1 * ve0; acc[1][1] += kd1 * ve1; acc[1][2] += kd1 * ve2; acc[1][3] += kd1 * ve3;
            acc[2][0] += kd2 * ve0; acc[2][1] += kd2 * ve1; acc[2][2] += kd2 * ve2; acc[2][3] += kd2 * ve3;
            acc[3][0] += kd3 * ve0; acc[3][1] += kd3 * ve1; acc[3][2] += kd3 * ve2; acc[3][3] += kd3 * ve3;
        }
        if (t < 64) ksacc += ks[0][t] + ks[1][t] + ks[2][t] + ks[3][t];
        __syncthreads();
    }

#pragma unroll
    for (int i = 0; i < 4; i++)
#pragma unroll
        for (int j = 0; j < 4; j++)
            atomicAdd(&kv[((size_t)bh * HDD + (td + i)) * HDD + te + j], acc[i][j]);
    if (t < 64) atomicAdd(&ksum[bh * HDD + t], ksacc);
}

// ---------------- out = (q.kv) / (q.ksum + eps), tf32-rounded output -------
__global__ void __launch_bounds__(256)
attn_kernel(const float* __restrict__ Q, const float* __restrict__ kv,
            const float* __restrict__ ksum, float* __restrict__ out) {
    const int bh = blockIdx.y;
    const int b = bh >> 4, h = bh & 15;
    const int t = threadIdx.x;
    const int w = t >> 5, l = t & 31;

    __shared__ float kvs[64 * 64];
    __shared__ float kss[64];
    __shared__ float qs[8][64];

    for (int i = t; i < 4096; i += 256) kvs[i] = kv[(size_t)bh * 4096 + i];
    if (t < 64) kss[t] = ksum[bh * 64 + t];
    __syncthreads();

    const int nbase = blockIdx.x * 128;
    for (int it = 0; it < 16; it++) {
        const int n = nbase + it * 8 + w;
        const float* qrow = Q + ((size_t)(b * NN + n)) * DIMM + h * HDD;
        float q0 = qrow[l];
        float q1 = qrow[l + 32];
        qs[w][l] = q0;
        qs[w][l + 32] = q1;
        __syncwarp();

        float p = q0 * kss[l] + q1 * kss[l + 32];
#pragma unroll
        for (int off = 16; off; off >>= 1) p += __shfl_xor_sync(0xffffffffu, p, off);
        const float denom = 1.0f / (p + 1e-6f);

        float a0 = 0.0f, a1 = 0.0f;
#pragma unroll 8
        for (int d = 0; d < 64; d++) {
            float qd = qs[w][d];
            a0 += qd * kvs[d * 64 + l];
            a1 += qd * kvs[d * 64 + l + 32];
        }
        float* orow = out + ((size_t)(b * NN + n)) * DIMM + h * HDD;
        orow[l] = to_tf32(a0 * denom);
        orow[l + 32] = to_tf32(a1 * denom);
        __syncwarp();
    }
}

// ---------------- launch ----------------
extern "C" void kernel_launch(void* const* d_in, const int* in_sizes, int n_in,
                              void* d_out, int out_size) {
    const float* query = (const float*)d_in[0];
    const float* key   = (const float*)d_in[1];
    const float* value = (const float*)d_in[2];
    const float* Wq = (const float*)d_in[3];
    const float* bq = (const float*)d_in[4];
    const float* Wk = (const float*)d_in[5];
    const float* bk = (const float*)d_in[6];
    const float* Wv = (const float*)d_in[7];
    const float* bv = (const float*)d_in[8];
    const float* Wo = (const float*)d_in[9];
    const float* bo = (const float*)d_in[10];
    const int* mask = (const int*)d_in[11];

    float *Qp, *Kp, *Vp, *Ap, *Wr, *KVp, *KSp;
    cudaGetSymbolAddress((void**)&Qp, g_Q);
    cudaGetSymbolAddress((void**)&Kp, g_K);
    cudaGetSymbolAddress((void**)&Vp, g_V);
    cudaGetSymbolAddress((void**)&Ap, g_A);
    cudaGetSymbolAddress((void**)&Wr, g_Wr);
    cudaGetSymbolAddress((void**)&KVp, g_kv);
    cudaGetSymbolAddress((void**)&KSp, g_ksum);

    cudaFuncSetAttribute(gemm_tc, cudaFuncAttributeMaxDynamicSharedMemorySize, DSMEM_BYTES);

    const int n4_w = (DIMM * DIMM) / 4;

    // launches 1-5: weight rounds + zero (ncu -s 5 then profiles the first GEMM)
    round_tf32_kernel<<<(n4_w + 255) / 256, 256>>>(Wq, Wr + 0 * (size_t)DIMM * DIMM, n4_w);
    round_tf32_kernel<<<(n4_w + 255) / 256, 256>>>(Wk, Wr + 1 * (size_t)DIMM * DIMM, n4_w);
    round_tf32_kernel<<<(n4_w + 255) / 256, 256>>>(Wv, Wr + 2 * (size_t)DIMM * DIMM, n4_w);
    round_tf32_kernel<<<(n4_w + 255) / 256, 256>>>(Wo, Wr + 3 * (size_t)DIMM * DIMM, n4_w);
    zero_kernel<<<1024, 256>>>(KVp, KSp);

    dim3 ggrid(DIMM / BN, MM / BM);   // (8, 128); n-fast for A-tile L2 reuse

    gemm_tc<<<ggrid, 256, DSMEM_BYTES>>>(query, Wr + 0 * (size_t)DIMM * DIMM, bq, nullptr, Qp, 1);
    gemm_tc<<<ggrid, 256, DSMEM_BYTES>>>(key,   Wr + 1 * (size_t)DIMM * DIMM, bk, mask,    Kp, 1);
    gemm_tc<<<ggrid, 256, DSMEM_BYTES>>>(value, Wr + 2 * (size_t)DIMM * DIMM, bv, nullptr, Vp, 0);

    kv_kernel<<<dim3(8, 64), 256>>>(Kp, Vp, KVp, KSp);
    attn_kernel<<<dim3(32, 64), 256>>>(Qp, KVp, KSp, Ap);

    gemm_tc<<<ggrid, 256, DSMEM_BYTES>>>(Ap, Wr + 3 * (size_t)DIMM * DIMM, bo, nullptr, (float*)d_out, 0);
}

// round 7
// speedup vs baseline: 1.1740x; 1.1204x over previous
#include <cuda_runtime.h>
#include <cuda_bf16.h>
#include <mma.h>
#include <cstdint>

using namespace nvcuda;

// Problem constants
#define BB 4
#define NN 4096
#define DIMM 1024
#define HH 16
#define HDD 64
#define MM (BB * NN)           // 16384 rows

// ---------------- scratch (device globals; no allocation allowed) ----------
__device__ float g_Q[(size_t)MM * DIMM];
__device__ float g_K[(size_t)MM * DIMM];
__device__ float g_V[(size_t)MM * DIMM];
__device__ float g_A[(size_t)MM * DIMM];
__device__ float g_Wr[4 * DIMM * DIMM];     // tf32-rounded Wq,Wk,Wv,Wo
__device__ float g_kv[BB * HH * HDD * HDD];
__device__ float g_ksum[BB * HH * HDD];

__device__ __forceinline__ float to_tf32(float x) {
    float r;
    asm("cvt.rna.tf32.f32 %0, %1;" : "=f"(r) : "f"(x));
    return r;
}

__device__ __forceinline__ void cp_async16(void* smem_ptr, const void* gmem_ptr) {
    unsigned int s = (unsigned int)__cvta_generic_to_shared(smem_ptr);
    asm volatile("cp.async.cg.shared.global [%0], [%1], 16;\n" :: "r"(s), "l"(gmem_ptr));
}

// ---------------- tf32 rounding pass (weights only) ----------------
__global__ void round_tf32_kernel(const float* __restrict__ src,
                                  float* __restrict__ dst, int n4) {
    int i = blockIdx.x * blockDim.x + threadIdx.x;
    if (i < n4) {
        float4 v = ((const float4*)src)[i];
        v.x = to_tf32(v.x); v.y = to_tf32(v.y);
        v.z = to_tf32(v.z); v.w = to_tf32(v.w);
        ((float4*)dst)[i] = v;
    }
}

// ---------------- GEMM: C[m,j] = act( A[m,:] . W[j,:] + bias[j] ) ----------
// M=16384, N=1024, K=1024. Block 128x128, K-step 16, 2-stage cp.async.
// W pre-rounded to tf32; A rounded in FRAGMENT REGISTERS after load.
#define KS 16
#define LDS_PAD 20          // 16 + 4 floats
#define STAGE_FLOATS (128 * LDS_PAD)

__global__ void __launch_bounds__(256, 2)
gemm_bias_act(const float* __restrict__ A, const float* __restrict__ W,
              const float* __restrict__ bias, const int* __restrict__ mask,
              float* __restrict__ C, int do_relu) {
    // smem: 2 stages x (A 128x20 + B 128x20) = 10240 floats = 40KB
    __shared__ __align__(16) float smem[2][2][STAGE_FLOATS];

    const int t = threadIdx.x;
    const int n0 = blockIdx.x * 128;
    const int m0 = blockIdx.y * 128;
    const int w = t >> 5;
    const int wm = w >> 1;   // 0..3 -> rows wm*32
    const int wn = w & 1;    // 0..1 -> cols wn*64

    wmma::fragment<wmma::accumulator, 16, 16, 8, float> acc[2][4];
#pragma unroll
    for (int i = 0; i < 2; i++)
#pragma unroll
        for (int j = 0; j < 4; j++)
            wmma::fill_fragment(acc[i][j], 0.0f);

    const int u0 = t;            // float4 id 0..255
    const int u1 = t + 256;      // 256..511
    const int rA0 = u0 >> 2, cA0 = (u0 & 3) * 4;
    const int rA1 = u1 >> 2, cA1 = (u1 & 3) * 4;

    const float* Abase = A + (size_t)m0 * DIMM;
    const float* Bbase = W + (size_t)n0 * DIMM;

    // prologue: stage 0
    {
        cp_async16(&smem[0][0][rA0 * LDS_PAD + cA0], Abase + (size_t)rA0 * DIMM + cA0);
        cp_async16(&smem[0][0][rA1 * LDS_PAD + cA1], Abase + (size_t)rA1 * DIMM + cA1);
        cp_async16(&smem[0][1][rA0 * LDS_PAD + cA0], Bbase + (size_t)rA0 * DIMM + cA0);
        cp_async16(&smem[0][1][rA1 * LDS_PAD + cA1], Bbase + (size_t)rA1 * DIMM + cA1);
        asm volatile("cp.async.commit_group;\n");
    }

    const int NSTG = DIMM / KS;   // 64
    for (int s = 0; s < NSTG; s++) {
        const int cur = s & 1;
        if (s + 1 < NSTG) {
            const int nxt = cur ^ 1;
            const int k0 = (s + 1) * KS;
            cp_async16(&smem[nxt][0][rA0 * LDS_PAD + cA0], Abase + (size_t)rA0 * DIMM + k0 + cA0);
            cp_async16(&smem[nxt][0][rA1 * LDS_PAD + cA1], Abase + (size_t)rA1 * DIMM + k0 + cA1);
            cp_async16(&smem[nxt][1][rA0 * LDS_PAD + cA0], Bbase + (size_t)rA0 * DIMM + k0 + cA0);
            cp_async16(&smem[nxt][1][rA1 * LDS_PAD + cA1], Bbase + (size_t)rA1 * DIMM + k0 + cA1);
            asm volatile("cp.async.commit_group;\n");
            asm volatile("cp.async.wait_group 1;\n");
        } else {
            asm volatile("cp.async.wait_group 0;\n");
        }
        __syncthreads();

        const float* As = smem[cur][0];
        const float* Bs = smem[cur][1];
#pragma unroll
        for (int kk = 0; kk < KS; kk += 8) {
            wmma::fragment<wmma::matrix_a, 16, 16, 8, wmma::precision::tf32, wmma::row_major> af[2];
            wmma::fragment<wmma::matrix_b, 16, 16, 8, wmma::precision::tf32, wmma::col_major> bf[4];
#pragma unroll
            for (int i = 0; i < 2; i++) {
                wmma::load_matrix_sync(af[i], As + (wm * 32 + i * 16) * LDS_PAD + kk, LDS_PAD);
                // round A in registers (RN) — B is pre-rounded, so MMA is exact
#pragma unroll
                for (int e = 0; e < af[i].num_elements; e++)
                    af[i].x[e] = to_tf32(af[i].x[e]);
            }
#pragma unroll
            for (int j = 0; j < 4; j++)
                wmma::load_matrix_sync(bf[j], Bs + (wn * 64 + j * 16) * LDS_PAD + kk, LDS_PAD);
#pragma unroll
            for (int i = 0; i < 2; i++)
#pragma unroll
                for (int j = 0; j < 4; j++)
                    wmma::mma_sync(acc[i][j], af[i], bf[j], acc[i][j]);
        }
        __syncthreads();
    }

    // ---- epilogue in two 64-row halves through smem (ldm 132, padded) ----
    float* Ct = &smem[0][0][0];   // needs 64*132 = 8448 floats <= 10240
#pragma unroll
    for (int half = 0; half < 2; half++) {
        if ((wm >> 1) == half) {
            const int wml = wm & 1;
#pragma unroll
            for (int i = 0; i < 2; i++)
#pragma unroll
                for (int j = 0; j < 4; j++)
                    wmma::store_matrix_sync(Ct + (wml * 32 + i * 16) * 132 + wn * 64 + j * 16,
                                            acc[i][j], 132, wmma::mem_row_major);
        }
        __syncthreads();
#pragma unroll
        for (int i = 0; i < 8; i++) {
            int u = t + i * 256;
            int r = u >> 5;
            int c = (u & 31) * 4;
            int row = m0 + half * 64 + r;
            float4 v = *(float4*)(Ct + r * 132 + c);
            v.x += bias[n0 + c + 0];
            v.y += bias[n0 + c + 1];
            v.z += bias[n0 + c + 2];
            v.w += bias[n0 + c + 3];
            if (do_relu) {
                v.x = fmaxf(v.x, 0.0f); v.y = fmaxf(v.y, 0.0f);
                v.z = fmaxf(v.z, 0.0f); v.w = fmaxf(v.w, 0.0f);
            }
            if (mask != nullptr && mask[row] != 0) {
                v.x = 0.0f; v.y = 0.0f; v.z = 0.0f; v.w = 0.0f;
            }
            *(float4*)(C + (size_t)row * DIMM + n0 + c) = v;
        }
        __syncthreads();
    }
}

// ---------------- zero kv / ksum ----------------
__global__ void zero_kernel(float* kv, float* ksum) {
    int idx = blockIdx.x * blockDim.x + threadIdx.x;
    if (idx < BB * HH * HDD * HDD) kv[idx] = 0.0f;
    if (idx < BB * HH * HDD) ksum[idx] = 0.0f;
}

// ---------------- kv[b,h,d,e] = sum_n K[b,n,h,d] * V[b,n,h,e]; ksum too ----
__global__ void __launch_bounds__(256)
kv_kernel(const float* __restrict__ K, const float* __restrict__ V,
          float* __restrict__ kv, float* __restrict__ ksum) {
    const int bh = blockIdx.y;
    const int b = bh >> 4, h = bh & 15;
    const int t = threadIdx.x;
    __shared__ float ks[4][64];
    __shared__ float vs[4][64];

    const int td = (t >> 4) << 2;
    const int te = (t & 15) << 2;
    float acc[4][4] = {};
    float ksacc = 0.0f;

    const int nbase0 = blockIdx.x * 512;
    for (int nb = 0; nb < 512; nb += 4) {
        const int n0 = nbase0 + nb;
#pragma unroll
        for (int j = 0; j < 2; j++) {
            int u = t + j * 256;
            int nn = (u >> 6) & 3;
            int d = u & 63;
            if (u < 256) {
                ks[nn][d] = K[((size_t)(b * NN + n0 + nn)) * DIMM + h * HDD + d];
            } else {
                vs[nn][d] = V[((size_t)(b * NN + n0 + nn)) * DIMM + h * HDD + d];
            }
        }
        __syncthreads();
#pragma unroll
        for (int nn = 0; nn < 4; nn++) {
            float kd0 = ks[nn][td + 0], kd1 = ks[nn][td + 1];
            float kd2 = ks[nn][td + 2], kd3 = ks[nn][td + 3];
            float ve0 = vs[nn][te + 0], ve1 = vs[nn][te + 1];
            float ve2 = vs[nn][te + 2], ve3 = vs[nn][te + 3];
            acc[0][0] += kd0 * ve0; acc[0][1] += kd0 * ve1; acc[0][2] += kd0 * ve2; acc[0][3] += kd0 * ve3;
            acc[1][0] += kd1 * ve0; acc[1][1] += kd1 * ve1; acc[1][2] += kd1 * ve2; acc[1][3] += kd1 * ve3;
            acc[2][0] += kd2 * ve0; acc[2][1] += kd2 * ve1; acc[2][2] += kd2 * ve2; acc[2][3] += kd2 * ve3;
            acc[3][0] += kd3 * ve0; acc[3][1] += kd3 * ve1; acc[3][2] += kd3 * ve2; acc[3][3] += kd3 * ve3;
        }
        if (t < 64) ksacc += ks[0][t] + ks[1][t] + ks[2][t] + ks[3][t];
        __syncthreads();
    }

#pragma unroll
    for (int i = 0; i < 4; i++)
#pragma unroll
        for (int j = 0; j < 4; j++)
            atomicAdd(&kv[((size_t)bh * HDD + (td + i)) * HDD + te + j], acc[i][j]);
    if (t < 64) atomicAdd(&ksum[bh * HDD + t], ksacc);
}

// ---------------- out = (q.kv) / (q.ksum + eps), tf32-rounded output -------
__global__ void __launch_bounds__(256)
attn_kernel(const float* __restrict__ Q, const float* __restrict__ kv,
            const float* __restrict__ ksum, float* __restrict__ out) {
    const int bh = blockIdx.y;
    const int b = bh >> 4, h = bh & 15;
    const int t = threadIdx.x;
    const int w = t >> 5, l = t & 31;

    __shared__ float kvs[64 * 64];
    __shared__ float kss[64];
    __shared__ float qs[8][64];

    for (int i = t; i < 4096; i += 256) kvs[i] = kv[(size_t)bh * 4096 + i];
    if (t < 64) kss[t] = ksum[bh * 64 + t];
    __syncthreads();

    const int nbase = blockIdx.x * 128;
    for (int it = 0; it < 16; it++) {
        const int n = nbase + it * 8 + w;
        const float* qrow = Q + ((size_t)(b * NN + n)) * DIMM + h * HDD;
        float q0 = qrow[l];
        float q1 = qrow[l + 32];
        qs[w][l] = q0;
        qs[w][l + 32] = q1;
        __syncwarp();

        float p = q0 * kss[l] + q1 * kss[l + 32];
#pragma unroll
        for (int off = 16; off; off >>= 1) p += __shfl_xor_sync(0xffffffffu, p, off);
        const float denom = 1.0f / (p + 1e-6f);

        float a0 = 0.0f, a1 = 0.0f;
#pragma unroll 8
        for (int d = 0; d < 64; d++) {
            float qd = qs[w][d];
            a0 += qd * kvs[d * 64 + l];
            a1 += qd * kvs[d * 64 + l + 32];
        }
        float* orow = out + ((size_t)(b * NN + n)) * DIMM + h * HDD;
        orow[l] = to_tf32(a0 * denom);
        orow[l + 32] = to_tf32(a1 * denom);
        __syncwarp();
    }
}

// ---------------- launch ----------------
extern "C" void kernel_launch(void* const* d_in, const int* in_sizes, int n_in,
                              void* d_out, int out_size) {
    const float* query = (const float*)d_in[0];
    const float* key   = (const float*)d_in[1];
    const float* value = (const float*)d_in[2];
    const float* Wq = (const float*)d_in[3];
    const float* bq = (const float*)d_in[4];
    const float* Wk = (const float*)d_in[5];
    const float* bk = (const float*)d_in[6];
    const float* Wv = (const float*)d_in[7];
    const float* bv = (const float*)d_in[8];
    const float* Wo = (const float*)d_in[9];
    const float* bo = (const float*)d_in[10];
    const int* mask = (const int*)d_in[11];

    float *Qp, *Kp, *Vp, *Ap, *Wr, *KVp, *KSp;
    cudaGetSymbolAddress((void**)&Qp, g_Q);
    cudaGetSymbolAddress((void**)&Kp, g_K);
    cudaGetSymbolAddress((void**)&Vp, g_V);
    cudaGetSymbolAddress((void**)&Ap, g_A);
    cudaGetSymbolAddress((void**)&Wr, g_Wr);
    cudaGetSymbolAddress((void**)&KVp, g_kv);
    cudaGetSymbolAddress((void**)&KSp, g_ksum);

    const int n4_w = (DIMM * DIMM) / 4;

    // launches 1-5: weight rounds + zero
    round_tf32_kernel<<<(n4_w + 255) / 256, 256>>>(Wq, Wr + 0 * (size_t)DIMM * DIMM, n4_w);
    round_tf32_kernel<<<(n4_w + 255) / 256, 256>>>(Wk, Wr + 1 * (size_t)DIMM * DIMM, n4_w);
    round_tf32_kernel<<<(n4_w + 255) / 256, 256>>>(Wv, Wr + 2 * (size_t)DIMM * DIMM, n4_w);
    round_tf32_kernel<<<(n4_w + 255) / 256, 256>>>(Wo, Wr + 3 * (size_t)DIMM * DIMM, n4_w);
    zero_kernel<<<1024, 256>>>(KVp, KSp);

    dim3 ggrid(DIMM / 128, MM / 128);   // (8, 128); n-fast for A-tile L2 reuse

    gemm_bias_act<<<ggrid, 256>>>(query, Wr + 0 * (size_t)DIMM * DIMM, bq, nullptr, Qp, 1);
    gemm_bias_act<<<ggrid, 256>>>(key,   Wr + 1 * (size_t)DIMM * DIMM, bk, mask,    Kp, 1);
    gemm_bias_act<<<ggrid, 256>>>(value, Wr + 2 * (size_t)DIMM * DIMM, bv, nullptr, Vp, 0);

    kv_kernel<<<dim3(8, 64), 256>>>(Kp, Vp, KVp, KSp);
    attn_kernel<<<dim3(32, 64), 256>>>(Qp, KVp, KSp, Ap);

    gemm_bias_act<<<ggrid, 256>>>(Ap, Wr + 3 * (size_t)DIMM * DIMM, bo, nullptr, (float*)d_out, 0);
}